// round 7
// baseline (speedup 1.0000x reference)
#include <cuda_runtime.h>
#include <math.h>
#include <stdint.h>

#define B      128
#define L      196
#define DTOP   64
#define DLOW   128
#define NE     512
#define NBOOK  15
#define EPSF   1e-8f
#define INV512 (1.0f/512.0f)

#define BM        32
#define KT        8
#define NTHREADS  128
#define ROWBLOCKS 7

#define QUANT_OFF 0ll
#define QUANT_CNT (4ll*B*L*DLOW)
#define DIFF_OFF  (QUANT_OFF + QUANT_CNT)
#define ID_OFF    (DIFF_OFF + 1)
#define ID_CNT    (4ll*B*L)
#define OT_OFF    (ID_OFF + ID_CNT)

__device__ float g_q4[B*L*DTOP];
__device__ float g_e2_top[NBOOK*NE];
__device__ float g_e2_lvl[4*NBOOK*NE];
__device__ float g_inve0[NBOOK*NE];
__device__ float g_embT_top[NBOOK*NE*DTOP];
__device__ float g_embT_lvl[4*NBOOK*NE*DLOW];

__device__ __forceinline__ unsigned smem_u32(const void* p) {
    unsigned r;
    asm("{.reg .u64 t; cvta.to.shared.u64 t, %1; cvt.u32.u64 %0, t;}" : "=r"(r) : "l"(p));
    return r;
}
__device__ __forceinline__ void cp16(unsigned dst, const void* src) {
    asm volatile("cp.async.cg.shared.global [%0], [%1], 16;" :: "r"(dst), "l"(src));
}
#define CP_COMMIT() asm volatile("cp.async.commit_group;" ::: "memory")
#define CP_WAIT0()  asm volatile("cp.async.wait_group 0;" ::: "memory")
#define CP_WAIT1()  asm volatile("cp.async.wait_group 1;" ::: "memory")
#define FMA2(a,x,e) asm("fma.rn.f32x2 %0, %1, %2, %0;" : "+l"(a) : "l"(x), "l"(e))

__global__ void norms_kernel(const float* __restrict__ cb_top,
                             const float* __restrict__ cb_lvl,
                             float* __restrict__ out)
{
    int k = threadIdx.x, book = blockIdx.x;
    if (book == 0 && k == 0) out[DIFF_OFF] = 0.0f;
    if (book < NBOOK) {
        const float* e = cb_top + (size_t)book * DTOP * NE;
        float s = 0.f;
        #pragma unroll 8
        for (int i = 0; i < DTOP; ++i) { float v = e[(size_t)i*NE + k]; s += v*v; }
        g_e2_top[book*NE + k] = s;
    } else {
        int bl = book - NBOOK;
        const float* e = cb_lvl + (size_t)bl * DLOW * NE;
        float s = 0.f;
        #pragma unroll 8
        for (int i = 0; i < DLOW; ++i) { float v = e[(size_t)i*NE + k]; s += v*v; }
        g_e2_lvl[bl*NE + k] = s;
        if (bl < NBOOK) g_inve0[bl*NE + k] = 1.0f / (sqrtf(s) + EPSF);
    }
}

__global__ void transpose_kernel(const float* __restrict__ cb_top,
                                 const float* __restrict__ cb_lvl)
{
    __shared__ float tile[32][33];
    int book = blockIdx.z;
    int k0 = blockIdx.x * 32, d0 = blockIdx.y * 32;
    const float* src; float* dst; int OD;
    if (book < NBOOK) {
        if (d0 >= DTOP) return;
        src = cb_top + (size_t)book * DTOP * NE;
        dst = g_embT_top + (size_t)book * NE * DTOP;  OD = DTOP;
    } else {
        int bl = book - NBOOK;
        src = cb_lvl + (size_t)bl * DLOW * NE;
        dst = g_embT_lvl + (size_t)bl * NE * DLOW;    OD = DLOW;
    }
    int tx = threadIdx.x, ty = threadIdx.y;
    #pragma unroll
    for (int dy = ty; dy < 32; dy += 8)
        tile[dy][tx] = src[(size_t)(d0 + dy) * NE + k0 + tx];
    __syncthreads();
    #pragma unroll
    for (int dy = ty; dy < 32; dy += 8)
        dst[(size_t)(k0 + dy) * OD + d0 + tx] = tile[tx][dy];
}

__device__ __forceinline__ float load_x_low(const float* __restrict__ in,
                                            int j, int b, int l, int c)
{
    if (c < DTOP) return in[((((size_t)j*B + b)*L + l)*DTOP) + c];
    return g_q4[(((size_t)b*L + l)*DTOP) + (c - DTOP)];
}
__device__ __forceinline__ float load_x_top(const float* __restrict__ in,
                                            int b, int l, int c)
{
    return in[((((size_t)4*B + b)*L + l)*DTOP) + c];
}

struct Epi {
    float minv[4][BM]; int mini[4][BM];
    float otm[4][BM], otz[4][BM], ott[4][BM];
    int ind[BM]; float dist[BM];
};

// per-k operand register set (loaded one k-step ahead)
struct EX { ulonglong2 ea, eb, ec, ed; float4 xa, xb; };

__device__ __forceinline__ void load_ex(EX& r, const char* ep0, const float* xk, int i,
                                        unsigned sw0, unsigned sw1,
                                        unsigned sw2, unsigned sw3)
{
    r.ea = *(const ulonglong2*)(ep0 + sw0 + i*2048);
    r.eb = *(const ulonglong2*)(ep0 + sw1 + i*2048);
    r.ec = *(const ulonglong2*)(ep0 + sw2 + i*2048);
    r.ed = *(const ulonglong2*)(ep0 + sw3 + i*2048);
    r.xa = *(const float4*)(xk + i*BM);
    r.xb = *(const float4*)(xk + i*BM + 4);
}

__device__ __forceinline__ void fma_block(unsigned long long (&acc)[8][8], const EX& v)
{
    float xr8[8] = {v.xa.x, v.xa.y, v.xa.z, v.xa.w, v.xb.x, v.xb.y, v.xb.z, v.xb.w};
    #pragma unroll
    for (int r = 0; r < 8; ++r) {
        unsigned long long xp;
        asm("mov.b64 %0, {%1,%1};" : "=l"(xp) : "f"(xr8[r]));
        FMA2(acc[r][0], xp, v.ea.x); FMA2(acc[r][1], xp, v.ea.y);
        FMA2(acc[r][2], xp, v.eb.x); FMA2(acc[r][3], xp, v.eb.y);
        FMA2(acc[r][4], xp, v.ec.x); FMA2(acc[r][5], xp, v.ec.y);
        FMA2(acc[r][6], xp, v.ed.x); FMA2(acc[r][7], xp, v.ed.y);
    }
}

// Block: 32 rows x 512 cols, 4 warps. Warp w covers cols [w*128, w*128+128).
// Lane: rg = lane>>3 (4 groups x 8 rows), co = lane&7 (8 groups x 16 cols).
template<int KDIM, bool IS_TOP>
__launch_bounds__(NTHREADS, 2)
__global__ void vq_gemm(const float* __restrict__ input_list,
                        const float* __restrict__ cb_top,
                        const float* __restrict__ cb_lvl,
                        const int*   __restrict__ label,
                        float*       __restrict__ out)
{
    __shared__ __align__(16) float e_s[2*KT*NE];    // 32 KB, swizzled
    __shared__ __align__(16) float x_s[KDIM*BM];    // 16/8 KB

    const int rb = blockIdx.x;
    const int b  = blockIdx.y;
    const int s  = blockIdx.z;
    const int j  = IS_TOP ? 4 : (3 - s);
    const int t  = label[b];
    const int rowbase = rb * BM;
    const int tid  = threadIdx.x;
    const int lane = tid & 31;
    const int w    = tid >> 5;
    const int rg   = lane >> 3;
    const int co   = lane & 7;
    const int rg8  = rg * 8;
    const int colb = w * 128 + co * 16;

    const float* emb = IS_TOP ? (cb_top + (size_t)t * DTOP * NE)
                              : (cb_lvl + ((size_t)j * NBOOK + t) * DLOW * NE);
    const unsigned e_base = smem_u32(e_s);

    const unsigned cb0 = (unsigned)(colb * 4);
    const unsigned sw0 = (cb0     ) ^ (((cb0     ) >> 3) & 0x70u);
    const unsigned sw1 = (cb0 + 16) ^ (((cb0 + 16) >> 3) & 0x70u);
    const unsigned sw2 = (cb0 + 32) ^ (((cb0 + 32) >> 3) & 0x70u);
    const unsigned sw3 = (cb0 + 48) ^ (((cb0 + 48) >> 3) & 0x70u);

    unsigned long long acc[8][8];
    #pragma unroll
    for (int r = 0; r < 8; ++r)
        #pragma unroll
        for (int p = 0; p < 8; ++p) acc[r][p] = 0ull;

    const int T = KDIM / KT;

#define FILL_E(BUF, TILE) do {                                                 \
    const char* esrc = (const char*)(emb + (size_t)(TILE) * KT * NE);          \
    const unsigned eb_ = e_base + (BUF) * (KT*NE*4);                           \
    _Pragma("unroll")                                                          \
    for (int kk = 0; kk < 8; ++kk) {                                           \
        unsigned off = (unsigned)(tid + kk*128) * 16u;                         \
        cp16(eb_ + (off ^ ((off >> 3) & 0x70u)), esrc + off);                  \
    }                                                                          \
    CP_COMMIT();                                                               \
} while (0)

#define COMPUTE(BUF) do {                                                      \
    const char* ep0 = (const char*)e_s + (BUF)*(KT*NE*4);                      \
    EX cur, nxt;                                                               \
    load_ex(cur, ep0, xk, 0, sw0, sw1, sw2, sw3);                              \
    _Pragma("unroll")                                                          \
    for (int i = 0; i < KT; ++i) {                                             \
        if (i + 1 < KT) load_ex(nxt, ep0, xk, i + 1, sw0, sw1, sw2, sw3);      \
        fma_block(acc, cur);                                                   \
        cur = nxt;                                                             \
    }                                                                          \
    xk += KT*BM;                                                               \
} while (0)

    FILL_E(0, 0);
    // stage x (coalesced global reads; rows beyond L zero-padded)
    {
        const int CSHIFT = (KDIM == 128) ? 7 : 6;
        for (int it = tid; it < BM*KDIM; it += NTHREADS) {
            int row = it >> CSHIFT, c = it & (KDIM - 1);
            int l = rowbase + row;
            float v = 0.f;
            if (l < L) v = IS_TOP ? load_x_top(input_list, b, l, c)
                                  : load_x_low(input_list, j, b, l, c);
            x_s[c*BM + row] = v;
        }
    }

    const float* xk = x_s + rg8;
    for (int tt = 0; tt < T; tt += 2) {
        FILL_E(1, tt + 1);
        CP_WAIT1(); __syncthreads();      // buf0 ready
        COMPUTE(0);
        __syncthreads();                  // buf0 free
        if (tt + 2 < T) { FILL_E(0, tt + 2); CP_WAIT1(); }
        else            { CP_WAIT0(); }
        __syncthreads();                  // buf1 ready
        COMPUTE(1);
        __syncthreads();                  // buf1 free
    }

    // ---- Epilogue (aliased over dead e_s) ----
    Epi* ep = (Epi*)e_s;
    const float* e2p = IS_TOP ? (g_e2_top + (size_t)t * NE)
                              : (g_e2_lvl + ((size_t)j * NBOOK + t) * NE);
    float e2v[16];
    #pragma unroll
    for (int c = 0; c < 16; c += 4)
        *(float4*)&e2v[c] = *(const float4*)&e2p[colb + c];
    const bool do_ot = (!IS_TOP) && (j == 0);
    float invev[16];
    if (do_ot) {
        const float* ip = g_inve0 + (size_t)t * NE;
        #pragma unroll
        for (int c = 0; c < 16; c += 4)
            *(float4*)&invev[c] = *(const float4*)&ip[colb + c];
    }

    #pragma unroll
    for (int r = 0; r < 8; ++r) {
        int row = rg8 + r;
        int l = rowbase + row;

        float gv[16];
        #pragma unroll
        for (int p = 0; p < 8; ++p)
            asm("mov.b64 {%0,%1}, %2;" : "=f"(gv[2*p]), "=f"(gv[2*p+1]) : "l"(acc[r][p]));

        float bv = 3.4e38f; int bi = NE;
        #pragma unroll
        for (int c = 0; c < 16; ++c) {
            float v = fmaf(-2.f, gv[c], e2v[c]);
            if (v < bv || (v == bv && colb + c < bi)) { bv = v; bi = colb + c; }
        }
        #pragma unroll
        for (int o = 1; o <= 4; o <<= 1) {
            float ov = __shfl_xor_sync(0xffffffffu, bv, o);
            int   oi = __shfl_xor_sync(0xffffffffu, bi, o);
            if (ov < bv || (ov == bv && oi < bi)) { bv = ov; bi = oi; }
        }
        if (co == 0 && l < L) { ep->minv[w][row] = bv; ep->mini[w][row] = bi; }

        if (do_ot) {
            float m = -3.4e38f;
            #pragma unroll
            for (int c = 0; c < 16; ++c) m = fmaxf(m, gv[c] * INV512);
            #pragma unroll
            for (int o = 1; o <= 4; o <<= 1)
                m = fmaxf(m, __shfl_xor_sync(0xffffffffu, m, o));
            float Z = 0.f, Tt = 0.f;
            #pragma unroll
            for (int c = 0; c < 16; ++c) {
                float pe = expf(gv[c] * INV512 - m);
                Z += pe;  Tt += gv[c] * invev[c] * pe;
            }
            #pragma unroll
            for (int o = 1; o <= 4; o <<= 1) {
                Z  += __shfl_xor_sync(0xffffffffu, Z,  o);
                Tt += __shfl_xor_sync(0xffffffffu, Tt, o);
            }
            if (co == 0 && l < L) { ep->otm[w][row] = m; ep->otz[w][row] = Z; ep->ott[w][row] = Tt; }
        }
    }
    __syncthreads();

    if (tid < BM) {
        int row = tid, l = rowbase + row;
        if (l < L) {
            float s2 = 0.f;
            #pragma unroll 8
            for (int c = 0; c < KDIM; ++c) { float v = x_s[c*BM + row]; s2 += v*v; }
            float bv = ep->minv[0][row]; int bi = ep->mini[0][row];
            #pragma unroll
            for (int ww = 1; ww < 4; ++ww) {
                float v = ep->minv[ww][row];
                if (v < bv) { bv = v; bi = ep->mini[ww][row]; }
            }
            ep->ind[row]  = bi;
            ep->dist[row] = s2 + bv;
            if (!IS_TOP)
                out[ID_OFF + ((size_t)s*B + b)*L + l] = (float)bi;
            if (do_ot) {
                float m = ep->otm[0][row];
                #pragma unroll
                for (int ww = 1; ww < 4; ++ww) m = fmaxf(m, ep->otm[ww][row]);
                float Z = 0.f, Tt = 0.f;
                #pragma unroll
                for (int ww = 0; ww < 4; ++ww) {
                    float sc = expf(ep->otm[ww][row] - m);
                    Z  += ep->otz[ww][row] * sc;
                    Tt += ep->ott[ww][row] * sc;
                }
                float invx = 1.0f / (sqrtf(s2) + EPSF);
                out[OT_OFF + (size_t)b*L + l] = (Z - invx * Tt) / Z;
            }
        }
    }
    __syncthreads();

    if (tid == 0) {
        int nval = L - rowbase; if (nval > BM) nval = BM;
        float sum = 0.f;
        for (int r = 0; r < nval; ++r) sum += ep->dist[r];
        atomicAdd(&out[DIFF_OFF], sum * (1.0f / (float)(L * KDIM)));
    }

    const int OD = IS_TOP ? DTOP : DLOW;
    const float* embT = IS_TOP ? (g_embT_top + (size_t)t * NE * DTOP)
                               : (g_embT_lvl + ((size_t)j * NBOOK + t) * NE * DLOW);
    for (int it = tid; it < BM*OD; it += NTHREADS) {
        int r = it / OD, c = it % OD;
        int l = rowbase + r;
        if (l >= L) continue;
        float v = embT[(size_t)ep->ind[r] * OD + c];
        if (IS_TOP)
            g_q4[((size_t)b*L + l)*DTOP + c] = v;
        else
            out[QUANT_OFF + (((size_t)s*B + b)*L + l)*DLOW + c] = v;
    }
#undef FILL_E
#undef COMPUTE
}

extern "C" void kernel_launch(void* const* d_in, const int* in_sizes, int n_in,
                              void* d_out, int out_size)
{
    const float* input_list = nullptr;
    const float* cb_top     = nullptr;
    const float* cb_lvl     = nullptr;
    const int*   label      = nullptr;

    for (int i = 0; i < n_in; ++i) {
        switch (in_sizes[i]) {
            case 8028160: input_list = (const float*)d_in[i]; break;
            case 491520:  cb_top     = (const float*)d_in[i]; break;
            case 3932160: cb_lvl     = (const float*)d_in[i]; break;
            case 128:     label      = (const int*)  d_in[i]; break;
        }
    }
    if (!input_list || !cb_top || !cb_lvl || !label) return;

    float* out = (float*)d_out;

    norms_kernel<<<NBOOK + 4*NBOOK, NE>>>(cb_top, cb_lvl, out);
    transpose_kernel<<<dim3(NE/32, 4, NBOOK + 4*NBOOK), dim3(32, 8)>>>(cb_top, cb_lvl);
    vq_gemm<DTOP, true ><<<dim3(ROWBLOCKS, B, 1), NTHREADS>>>(input_list, cb_top, cb_lvl, label, out);
    vq_gemm<DLOW, false><<<dim3(ROWBLOCKS, B, 4), NTHREADS>>>(input_list, cb_top, cb_lvl, label, out);
}